// round 1
// baseline (speedup 1.0000x reference)
#include <cuda_runtime.h>
#include <stdint.h>

#define B_ 4
#define C_ 64
#define H_ 64
#define W_ 192
#define D_ 24
#define HW_ (H_*W_)

// Scratch: Q/K feature maps in [vol][b][h*w][c] layout (channel-contiguous).
// g_Q[0]=Q1 (qw@x), g_Q[1]=Q2 (qw@y); g_K[0]=K1 (kw@y), g_K[1]=K2 (kw@x).
__device__ float g_Q[2][B_][HW_][C_];
__device__ float g_K[2][B_][HW_][C_];

__device__ __forceinline__ unsigned long long pack2(float x) {
    unsigned r = __float_as_uint(x);
    unsigned long long p;
    asm("mov.b64 %0, {%1, %1};" : "=l"(p) : "r"(r));
    return p;
}
__device__ __forceinline__ unsigned long long ffma2(unsigned long long a,
                                                    unsigned long long b,
                                                    unsigned long long c) {
    unsigned long long d;
    asm("fma.rn.f32x2 %0, %1, %2, %3;" : "=l"(d) : "l"(a), "l"(b), "l"(c));
    return d;
}
__device__ __forceinline__ float2 unpack2(unsigned long long p) {
    unsigned lo, hi;
    asm("mov.b64 {%0, %1}, %2;" : "=r"(lo), "=r"(hi) : "l"(p));
    return make_float2(__uint_as_float(lo), __uint_as_float(hi));
}

// ---------------------------------------------------------------------------
// Kernel 1: conv1x1. Block = (64-pixel tile, batch b, src in {x,y}).
// Each block computes both qw- and kw- projections of its pixel tile.
// 256 threads: 4 threads/pixel, 16 output channels each, fp32x2 packed FMA.
// ---------------------------------------------------------------------------
__global__ __launch_bounds__(256) void conv1x1_kernel(
    const float* __restrict__ x, const float* __restrict__ y,
    const float* __restrict__ qw, const float* __restrict__ qb,
    const float* __restrict__ kw, const float* __restrict__ kb)
{
    __shared__ float in_s[64][64];     // [channel][pixel]
    __shared__ float wt_s[64][68];     // transposed weights [i][o], 272B stride (16B-aligned)
    const int b      = blockIdx.y;
    const int tile   = blockIdx.x;     // 0..191, 64 flat pixels each
    const int srcIdx = blockIdx.z;     // 0=x, 1=y
    const float* src = (srcIdx == 0) ? x : y;
    const int tid = threadIdx.x;
    const int pix = tid & 63;
    const int q4  = tid >> 6;          // 0..3 -> output channel quarter

    const float* sp = src + ((size_t)b * C_) * HW_ + tile * 64;
    #pragma unroll
    for (int e = tid; e < 64 * 64; e += 256)
        in_s[e >> 6][e & 63] = sp[(size_t)(e >> 6) * HW_ + (e & 63)];

    for (int m = 0; m < 2; ++m) {
        const float* w    = (m == 0) ? qw : kw;
        const float* bias = (m == 0) ? qb : kb;
        __syncthreads();
        #pragma unroll
        for (int e = tid; e < 64 * 64; e += 256)
            wt_s[e & 63][e >> 6] = w[e];   // w[o][i] -> wt_s[i][o]
        __syncthreads();

        unsigned long long acc[8];
        #pragma unroll
        for (int k = 0; k < 8; k++) acc[k] = 0ull;

        #pragma unroll 16
        for (int i = 0; i < 64; ++i) {
            unsigned long long x2 = pack2(in_s[i][pix]);
            const ulonglong2* wr = (const ulonglong2*)&wt_s[i][q4 * 16];
            #pragma unroll
            for (int k = 0; k < 4; k++) {
                ulonglong2 wv = wr[k];               // LDS.128 (warp-uniform: broadcast)
                acc[2*k]   = ffma2(wv.x, x2, acc[2*k]);
                acc[2*k+1] = ffma2(wv.y, x2, acc[2*k+1]);
            }
        }

        float v[16];
        #pragma unroll
        for (int k = 0; k < 8; k++) {
            float2 t = unpack2(acc[k]);
            v[2*k]   = t.x + bias[q4 * 16 + 2*k];
            v[2*k+1] = t.y + bias[q4 * 16 + 2*k + 1];
        }
        float* outp = (m == 0) ? &g_Q[srcIdx][b][tile * 64 + pix][q4 * 16]
                               : &g_K[srcIdx ^ 1][b][tile * 64 + pix][q4 * 16];
        #pragma unroll
        for (int j = 0; j < 4; j++)
            ((float4*)outp)[j] = make_float4(v[4*j], v[4*j+1], v[4*j+2], v[4*j+3]);
    }
}

// ---------------------------------------------------------------------------
// Kernel 2: cost volume. Block = (h, b, vol). Prologue: y-blend the two K rows
// (validity folded into weights) into smem Kb[192][64]. Main loop: warp covers
// 4 w-positions x 8 channel-groups; per (d,w): 2 x-corner gathers (conflict-free
// LDS.128), blend+dot, shfl reduce over channel groups.
// ---------------------------------------------------------------------------
__global__ __launch_bounds__(256) void cost_kernel(
    const float* __restrict__ d1, const float* __restrict__ d2,
    float* __restrict__ out)
{
    __shared__ float kb_s[W_][C_];     // 48 KB
    const int h = blockIdx.x, b = blockIdx.y, vol = blockIdx.z;
    const int tid = threadIdx.x;

    // y-row blend (ys depends only on h)
    float ys  = h * (64.0f / 63.0f) - 0.5f;
    float y0f = floorf(ys);
    float ty  = ys - y0f;
    int iy0 = (int)y0f;
    int iy1 = iy0 + 1;
    float wy0 = (iy0 >= 0 && iy0 < H_) ? (1.0f - ty) : 0.0f;
    float wy1 = (iy1 >= 0 && iy1 < H_) ? ty : 0.0f;
    int y0c = min(max(iy0, 0), H_ - 1);
    int y1c = min(max(iy1, 0), H_ - 1);
    const float4* k0 = (const float4*)&g_K[vol][b][y0c * W_][0];
    const float4* k1 = (const float4*)&g_K[vol][b][y1c * W_][0];
    float4* kbp = (float4*)&kb_s[0][0];
    #pragma unroll
    for (int e = tid; e < W_ * C_ / 4; e += 256) {
        float4 a = k0[e], c = k1[e];
        kbp[e] = make_float4(wy0 * a.x + wy1 * c.x, wy0 * a.y + wy1 * c.y,
                             wy0 * a.z + wy1 * c.z, wy0 * a.w + wy1 * c.w);
    }
    __syncthreads();

    const int warp = tid >> 5, lane = tid & 31;
    const int wsub = lane >> 3, cg = lane & 7;   // 4 w-positions x 8 ch-groups
    const float* dispb = ((vol == 0) ? d1 : d2) + ((size_t)b * D_) * HW_ + h * W_;
    float* outb = out + (((size_t)vol * B_ + b) * (size_t)D_) * HW_ + h * W_;

    #pragma unroll 1
    for (int pass = 0; pass < 6; ++pass) {
        int w = pass * 32 + warp * 4 + wsub;
        const float* qp = &g_Q[vol][b][h * W_ + w][0];
        float4 qA = *(const float4*)(qp + cg * 4);        // ch cg*4..+3
        float4 qB = *(const float4*)(qp + 32 + cg * 4);   // ch 32+cg*4..+3

        #pragma unroll 2
        for (int d = 0; d < D_; ++d) {
            float disp = __ldg(&dispb[d * HW_ + w]);
            float xs  = disp * (192.0f / 191.0f) - 0.5f;
            float x0f = floorf(xs);
            float tx  = xs - x0f;
            int ix0 = (int)x0f;
            float wx0 = (ix0 >= 0 && ix0 < W_) ? (1.0f - tx) : 0.0f;
            float wx1 = (ix0 + 1 >= 0 && ix0 + 1 < W_) ? tx : 0.0f;
            int x0c = min(max(ix0, 0), W_ - 1);
            int x1c = min(max(ix0 + 1, 0), W_ - 1);
            const float* r0 = &kb_s[x0c][0];
            const float* r1 = &kb_s[x1c][0];
            float4 a0 = *(const float4*)(r0 + cg * 4);
            float4 b0 = *(const float4*)(r0 + 32 + cg * 4);
            float4 a1 = *(const float4*)(r1 + cg * 4);
            float4 b1 = *(const float4*)(r1 + 32 + cg * 4);

            float s;
            s  = qA.x * (wx0 * a0.x + wx1 * a1.x);
            s += qA.y * (wx0 * a0.y + wx1 * a1.y);
            s += qA.z * (wx0 * a0.z + wx1 * a1.z);
            s += qA.w * (wx0 * a0.w + wx1 * a1.w);
            s += qB.x * (wx0 * b0.x + wx1 * b1.x);
            s += qB.y * (wx0 * b0.y + wx1 * b1.y);
            s += qB.z * (wx0 * b0.z + wx1 * b1.z);
            s += qB.w * (wx0 * b0.w + wx1 * b1.w);

            s += __shfl_xor_sync(0xffffffffu, s, 1);
            s += __shfl_xor_sync(0xffffffffu, s, 2);
            s += __shfl_xor_sync(0xffffffffu, s, 4);
            if (cg == 0) outb[d * HW_ + w] = s * (1.0f / 64.0f);
        }
    }
}

extern "C" void kernel_launch(void* const* d_in, const int* in_sizes, int n_in,
                              void* d_out, int out_size) {
    const float* x  = (const float*)d_in[0];
    const float* y  = (const float*)d_in[1];
    const float* d1 = (const float*)d_in[2];
    const float* d2 = (const float*)d_in[3];
    // ndisp (scalar int) may or may not occupy a slot; detect via element count.
    int wbase = (in_sizes[4] == 1) ? 5 : 4;
    const float* qw = (const float*)d_in[wbase + 0];
    const float* qb = (const float*)d_in[wbase + 1];
    const float* kw = (const float*)d_in[wbase + 2];
    const float* kb = (const float*)d_in[wbase + 3];
    float* out = (float*)d_out;

    conv1x1_kernel<<<dim3(192, B_, 2), 256>>>(x, y, qw, qb, kw, kb);
    cost_kernel<<<dim3(H_, B_, 2), 256>>>(d1, d2, out);
}